// round 8
// baseline (speedup 1.0000x reference)
#include <cuda_runtime.h>
#include <cuda_fp16.h>
#include <math.h>

// Problem dims (fixed by the dataset)
#define NN 4
#define HH 512
#define WW 512
#define CC 64

#define CPB     64                 // channels per block = full row
#define THREADS 512
#define ROWLEN  512
#define NCHUNK  16                 // one warp per chunk; lane = half2 channel pair
#define CLEN    (ROWLEN / NCHUNK)  // 32
#define LWARM   12                 // warm-up: err ~ 0.5^13 ~ 1.2e-4 x O(0.5)
#define H2PW    (CPB / 2)          // half2 per scan-site = 32
#define VECH    (ROWLEN * CPB / 8) // uint4 (8 halves) per fp16 tile = 4096
#define SMEM_BYTES (ROWLEN * CPB * 2) // 65536 (fp16 tile -> 3 CTAs/SM)

// Intermediate (W-filtered) image in fp16, same NHWC index space as x.
__device__ __half g_scratch[(size_t)NN * HH * WW * CC];

// Pass 1: IIR along W. One block per (n*H) row, all 64 channels.
// fp32 x -> fp16 smem tile -> fwd scan in place -> bwd scan streamed
// straight to g_scratch from registers (no final smem pass, no final sync).
__global__ void __launch_bounds__(THREADS, 3)
pass1_kernel(const float* __restrict__ x) {
    extern __shared__ __half2 s2[];
    uint4* s4 = reinterpret_cast<uint4*>(s2);

    const int    nh   = blockIdx.x;                 // n*HH + h
    const size_t base = (size_t)nh * (WW * CC);

    // Load + fp32->fp16: per w, 64 ch = 8 uint4 of 8 halves.
    #pragma unroll
    for (int i = threadIdx.x; i < VECH; i += THREADS) {
        const int w = i >> 3;
        const int q = i & 7;
        const float4 a = __ldcs((const float4*)(x + base + (size_t)w * CC + q * 8));
        const float4 b = __ldcs((const float4*)(x + base + (size_t)w * CC + q * 8 + 4));
        __half2 hv[4];
        hv[0] = __floats2half2_rn(a.x, a.y);
        hv[1] = __floats2half2_rn(a.z, a.w);
        hv[2] = __floats2half2_rn(b.x, b.y);
        hv[3] = __floats2half2_rn(b.z, b.w);
        s4[w * 8 + q] = *(uint4*)hv;
    }
    __syncthreads();

    const int c2    = threadIdx.x & 31;
    const int chunk = threadIdx.x >> 5;
    const int w0    = chunk * CLEN;
    const int w1    = w0 + CLEN;

    // ---- forward warm-up (read-only) ----
    int ws = w0 - LWARM; if (ws < 0) ws = 0;
    float2 carry = __half22float2(s2[ws * H2PW + c2]);
    for (int w = ws; w < w0; ++w) {
        const float2 v = __half22float2(s2[w * H2PW + c2]);
        carry.x = fmaf(0.5f, carry.x, 0.5f * v.x);
        carry.y = fmaf(0.5f, carry.y, 0.5f * v.y);
    }
    __syncthreads();

    // ---- forward scan, in place ----
    #pragma unroll
    for (int w = w0; w < w1; ++w) {
        const float2 v = __half22float2(s2[w * H2PW + c2]);
        carry.x = fmaf(0.5f, carry.x, 0.5f * v.x);
        carry.y = fmaf(0.5f, carry.y, 0.5f * v.y);
        s2[w * H2PW + c2] = __floats2half2_rn(carry.x, carry.y);
    }
    __syncthreads();

    // ---- backward warm-up (read-only on finalized y_f) ----
    int we = w1 - 1 + LWARM; if (we > ROWLEN - 1) we = ROWLEN - 1;
    carry = __half22float2(s2[we * H2PW + c2]);
    for (int w = we - 1; w >= w1; --w) {
        const float2 v = __half22float2(s2[w * H2PW + c2]);
        carry.x = fmaf(0.5f, carry.x, 0.5f * v.x);
        carry.y = fmaf(0.5f, carry.y, 0.5f * v.y);
    }
    // No sync needed: backward phase only READS forward results.

    // ---- backward scan, streamed to gmem (128B/warp-step) ----
    #pragma unroll
    for (int w = w1 - 1; w >= w0; --w) {
        const float2 v = __half22float2(s2[w * H2PW + c2]);
        carry.x = fmaf(0.5f, carry.x, 0.5f * v.x);
        carry.y = fmaf(0.5f, carry.y, 0.5f * v.y);
        const __half2 hv = __floats2half2_rn(carry.x, carry.y);
        __stcs((unsigned int*)(g_scratch + base + (size_t)w * CC) + c2,
               *(const unsigned int*)&hv);
    }
}

// Pass 2: IIR along H on the scratch; backward scan fused with the residual
// mix epilogue (x load + out store straight from the carry registers).
__global__ void __launch_bounds__(THREADS, 3)
pass2_kernel(const float* __restrict__ x,
             const float* __restrict__ alpha,
             float*       __restrict__ out) {
    extern __shared__ __half2 s2[];
    uint4* s4 = reinterpret_cast<uint4*>(s2);
    __shared__ __align__(16) float sm[CPB];

    const int    nw   = blockIdx.x;                 // n*WW + w
    const int    n    = nw >> 9;
    const int    w    = nw & 511;
    const size_t base = (size_t)n * (HH * WW * CC) + (size_t)w * CC;

    if (threadIdx.x < CPB)
        sm[threadIdx.x] = 1.0f / (1.0f + expf(-alpha[threadIdx.x]));

    // Raw fp16 copy scratch -> smem: per h, 8 uint4 (128B row-step).
    #pragma unroll
    for (int i = threadIdx.x; i < VECH; i += THREADS) {
        const int h = i >> 3;
        const int q = i & 7;
        s4[h * 8 + q] =
            __ldcs((const uint4*)(g_scratch + base + (size_t)h * (WW * CC) + q * 8));
    }
    __syncthreads();

    const int c2    = threadIdx.x & 31;
    const int chunk = threadIdx.x >> 5;
    const int h0    = chunk * CLEN;
    const int h1    = h0 + CLEN;

    // ---- forward warm-up ----
    int hs = h0 - LWARM; if (hs < 0) hs = 0;
    float2 carry = __half22float2(s2[hs * H2PW + c2]);
    for (int h = hs; h < h0; ++h) {
        const float2 v = __half22float2(s2[h * H2PW + c2]);
        carry.x = fmaf(0.5f, carry.x, 0.5f * v.x);
        carry.y = fmaf(0.5f, carry.y, 0.5f * v.y);
    }
    __syncthreads();

    // ---- forward scan, in place ----
    #pragma unroll
    for (int h = h0; h < h1; ++h) {
        const float2 v = __half22float2(s2[h * H2PW + c2]);
        carry.x = fmaf(0.5f, carry.x, 0.5f * v.x);
        carry.y = fmaf(0.5f, carry.y, 0.5f * v.y);
        s2[h * H2PW + c2] = __floats2half2_rn(carry.x, carry.y);
    }
    __syncthreads();

    // ---- backward warm-up ----
    int he = h1 - 1 + LWARM; if (he > ROWLEN - 1) he = ROWLEN - 1;
    carry = __half22float2(s2[he * H2PW + c2]);
    for (int h = he - 1; h >= h1; --h) {
        const float2 v = __half22float2(s2[h * H2PW + c2]);
        carry.x = fmaf(0.5f, carry.x, 0.5f * v.x);
        carry.y = fmaf(0.5f, carry.y, 0.5f * v.y);
    }
    // No sync needed: backward phase only READS forward results; sm[] was
    // written before the first __syncthreads.

    // ---- backward scan + fused residual epilogue (256B/warp-step) ----
    const float2 mv = *(const float2*)(&sm[c2 * 2]);
    #pragma unroll
    for (int h = h1 - 1; h >= h0; --h) {
        const float2 v = __half22float2(s2[h * H2PW + c2]);
        carry.x = fmaf(0.5f, carry.x, 0.5f * v.x);
        carry.y = fmaf(0.5f, carry.y, 0.5f * v.y);
        const size_t g = base + (size_t)h * (WW * CC) + c2 * 2;
        const float2 xv = __ldcs((const float2*)(x + g));
        float2 o;
        o.x = fmaf(mv.x, carry.x - xv.x, xv.x);
        o.y = fmaf(mv.y, carry.y - xv.y, xv.y);
        __stcs((float2*)(out + g), o);
    }
}

extern "C" void kernel_launch(void* const* d_in, const int* in_sizes, int n_in,
                              void* d_out, int out_size) {
    const float* x     = (const float*)d_in[0];
    const float* alpha = (const float*)d_in[1];
    float*       out   = (float*)d_out;

    // >48KB dynamic smem opt-in (idempotent, capture-safe).
    cudaFuncSetAttribute(pass1_kernel,
                         cudaFuncAttributeMaxDynamicSharedMemorySize, SMEM_BYTES);
    cudaFuncSetAttribute(pass2_kernel,
                         cudaFuncAttributeMaxDynamicSharedMemorySize, SMEM_BYTES);

    pass1_kernel<<<NN * HH, THREADS, SMEM_BYTES>>>(x);
    pass2_kernel<<<NN * WW, THREADS, SMEM_BYTES>>>(x, alpha, out);
}